// round 1
// baseline (speedup 1.0000x reference)
#include <cuda_runtime.h>

#define NS   48000
#define NIN  400
#define NSEG 401      // head(60) + 399 interior(120) + tail(60)
#define NB   16
#define NM   64
#define NROWS (NB*NM)

// Scratch (allocation-free): per-row fp64 segment prefixes + shared frac-cumsum table
__device__ double g_B[(size_t)NROWS * NSEG];   // ~3.3 MB
__device__ float  g_F1[NSEG * 120];            // 192 KB

// Exact replica of the reference's fp32 position/frac computation.
// Must NOT be FMA-contracted (ref does mul-then-sub with separate roundings).
__device__ __forceinline__ float ref_frac(int j) {
    const float SCALE = 400.0f / 48000.0f;   // fl32(1/120), matches jax weak-typed scalar
    float pos = __fsub_rn(__fmul_rn(__fadd_rn((float)j, 0.5f), SCALE), 0.5f);
    pos = fminf(fmaxf(pos, 0.0f), 399.0f);
    float fi = floorf(pos);
    return __fsub_rn(pos, fi);               // exact (Sterbenz)
}

// Kernel A: row-independent cumulative-frac table, fp64 accumulate -> fp32 store.
__global__ void f1_kernel() {
    int s = threadIdx.x;
    if (s > 400) return;
    int cnt   = (s == 0 || s == 400) ? 60 : 120;
    int start = (s == 0) ? 0 : 60 + (s - 1) * 120;
    double acc = 0.0;
    for (int m = 0; m < cnt; m++) {
        acc += (double)ref_frac(start + m);
        g_F1[s * 120 + m] = (float)acc;
    }
}

// Kernel B: per-row exclusive prefix over segment sums, fp64.
// segsum(s) = cnt*f[i] + (f[i+1]-f[i]) * Sum(frac over segment)
__global__ void scan_kernel(const float* __restrict__ params) {
    int r = blockIdx.x;                 // 0..1023 : b*64 + mode
    int b = r >> 6, mode = r & 63;
    const float* F = params + (size_t)(b * 192 + mode) * 400;  // channel 0 = freqs
    int t = threadIdx.x;                // 512 threads
    __shared__ double sh[512];
    double v = 0.0;
    if (t == 0) {
        v = 60.0 * (double)F[0];        // head: frac == 0 for all 60 samples
    } else if (t <= 399) {
        int i = t - 1;
        double f0 = F[i], f1 = F[i + 1];
        v = 120.0 * f0 + (f1 - f0) * (double)g_F1[t * 120 + 119];
    }
    sh[t] = v;
    __syncthreads();
    for (int off = 1; off < 512; off <<= 1) {
        double add = (t >= off) ? sh[t - off] : 0.0;
        __syncthreads();
        sh[t] += add;
        __syncthreads();
    }
    if (t <= 400)
        g_B[(size_t)r * NSEG + t] = (t == 0) ? 0.0 : sh[t - 1];
}

// Kernel C: main synthesis. Block = (segment s, batch b); thread = sample m in segment.
__global__ void __launch_bounds__(128) synth_kernel(const float* __restrict__ params,
                                                    float* __restrict__ out) {
    int s = blockIdx.x, b = blockIdx.y;
    __shared__ float4 md[64];   // (ph_base_reduced, f0, dF, a0)
    __shared__ float  das[64];  // dA
    int tid = threadIdx.x;

    if (tid < 64) {
        int mode = tid;
        const float* F = params + (size_t)(b * 192 + mode) * 400;
        const float* A = F + 64 * 400;      // channel 1 = amps
        const float* P = F + 128 * 400;     // channel 2 = phase
        int i  = (s == 0) ? 0 : ((s <= 399) ? s - 1 : 399);
        int i1 = min(i + 1, 399);
        float f0 = F[i];
        float dw = F[i1] - f0;
        float a0 = A[i];
        float da = A[i1] - a0;
        // phase base = B[row][s] + phase[row][0], reduced mod 2pi in fp64 once
        double t = g_B[(size_t)(b * 64 + mode) * NSEG + s] + (double)P[0];
        double kk = rint(t * 0.15915494309189535);
        double rr = t - kk * 6.283185307179586;
        md[mode]  = make_float4((float)rr, f0, dw, a0);
        das[mode] = da;
    }
    __syncthreads();

    int cnt = (s == 0 || s == 400) ? 60 : 120;
    int m = tid;
    if (m >= cnt) return;
    int start = (s == 0) ? 0 : 60 + (s - 1) * 120;
    int j = start + m;

    float frac = ref_frac(j);               // exact ref-style frac (for amp interp)
    float F1s  = g_F1[s * 120 + m];         // Sum of frac within segment, inclusive
    float t1   = (float)(m + 1);

    const float INV2PI = 0.15915493667125702f;
    const float PI2_A  = 6.2831854820251465f;
    const float PI2_B  = -1.7484556e-07f;

    float acc = 0.0f;
#pragma unroll 16
    for (int k = 0; k < 64; k++) {
        float4 v = md[k];
        // S_j = ph_base + (m+1)*f0 + dF * SumFrac   (|ph| <= ~600)
        float ph = fmaf(v.z, F1s, fmaf(t1, v.y, v.x));
        // Cody-Waite reduce to [-pi, pi], then fast hardware sin (RRO+MUFU.SIN)
        float kr = rintf(ph * INV2PI);
        float r  = fmaf(-kr, PI2_A, ph);
        r        = fmaf(-kr, PI2_B, r);
        float a  = fmaf(das[k], frac, v.w);
        acc = fmaf(a, __sinf(r), acc);
    }
    out[(size_t)b * NS + j] = acc;
}

extern "C" void kernel_launch(void* const* d_in, const int* in_sizes, int n_in,
                              void* d_out, int out_size) {
    const float* params = (const float*)d_in[0];
    float* out = (float*)d_out;
    f1_kernel<<<1, 512>>>();
    scan_kernel<<<NROWS, 512>>>(params);
    dim3 grid(NSEG, NB);
    synth_kernel<<<grid, 128>>>(params, out);
}

// round 2
// speedup vs baseline: 1.6888x; 1.6888x over previous
#include <cuda_runtime.h>

#define NS   48000
#define NIN  400
#define NSEG 401      // head(60) + 399 interior(120) + tail(60)
#define NB   16
#define NM   64
#define NROWS (NB*NM)

// Scratch (allocation-free): per-row fp64 segment prefixes + shared frac-cumsum table
__device__ double g_B[(size_t)NROWS * NSEG];   // ~3.3 MB
__device__ float  g_F1[NSEG * 120];            // 192 KB

// Exact replica of the reference's fp32 position/frac computation.
// Must NOT be FMA-contracted (ref does mul-then-sub with separate roundings).
__device__ __forceinline__ float ref_frac(int j) {
    const float SCALE = 400.0f / 48000.0f;   // fl32(1/120)
    float pos = __fsub_rn(__fmul_rn(__fadd_rn((float)j, 0.5f), SCALE), 0.5f);
    pos = fminf(fmaxf(pos, 0.0f), 399.0f);
    float fi = floorf(pos);
    return __fsub_rn(pos, fi);               // exact (Sterbenz)
}

// Kernel A: row-independent cumulative-frac table.
// One block per segment; 128-thread fp64 shuffle scan replaces the old
// single-block serial version (28.9us -> ~2us).
__global__ void __launch_bounds__(128) f1_kernel() {
    int s = blockIdx.x;
    int cnt   = (s == 0 || s == 400) ? 60 : 120;
    int start = (s == 0) ? 0 : 60 + (s - 1) * 120;
    int m = threadIdx.x;
    double v = (m < cnt) ? (double)ref_frac(start + m) : 0.0;

    int lane = m & 31, w = m >> 5;
    #pragma unroll
    for (int off = 1; off < 32; off <<= 1) {
        double n = __shfl_up_sync(0xFFFFFFFFu, v, off);
        if (lane >= off) v += n;
    }
    __shared__ double wsum[4];
    if (lane == 31) wsum[w] = v;
    __syncthreads();
    double base = 0.0;
    #pragma unroll
    for (int i = 0; i < 3; i++)
        if (i < w) base += wsum[i];
    if (m < cnt) g_F1[s * 120 + m] = (float)(v + base);
}

// Kernel B: per-row exclusive prefix over segment sums, fp64, shuffle-based.
// segsum(s) = cnt*f[i] + (f[i+1]-f[i]) * Sum(frac over segment)
__global__ void __launch_bounds__(512) scan_kernel(const float* __restrict__ params) {
    int r = blockIdx.x;                 // 0..1023 : b*64 + mode
    int b = r >> 6, mode = r & 63;
    const float* F = params + (size_t)(b * 192 + mode) * 400;  // channel 0 = freqs
    int t = threadIdx.x;                // 512 threads, values live in t=0..400

    double v = 0.0;
    if (t == 0) {
        v = 60.0 * (double)F[0];        // head: frac == 0 for all 60 samples
    } else if (t <= 399) {
        int i = t - 1;
        double f0 = F[i], f1 = F[i + 1];
        v = 120.0 * f0 + (f1 - f0) * (double)g_F1[t * 120 + 119];
    }

    int lane = t & 31, w = t >> 5;
    double sv = v;
    #pragma unroll
    for (int off = 1; off < 32; off <<= 1) {
        double n = __shfl_up_sync(0xFFFFFFFFu, sv, off);
        if (lane >= off) sv += n;
    }
    __shared__ double wsum[16];
    if (lane == 31) wsum[w] = sv;
    __syncthreads();
    if (w == 0) {
        double x = (lane < 16) ? wsum[lane] : 0.0;
        #pragma unroll
        for (int off = 1; off < 16; off <<= 1) {
            double n = __shfl_up_sync(0xFFFFFFFFu, x, off);
            if (lane >= off) x += n;
        }
        if (lane < 16) wsum[lane] = x;
    }
    __syncthreads();
    double incl = sv + ((w > 0) ? wsum[w - 1] : 0.0);
    if (t <= 400)
        g_B[(size_t)r * NSEG + t] = incl - v;   // exclusive prefix
}

// Kernel C: main synthesis. Block = (segment s, batch b); thread = sample m in segment.
__global__ void __launch_bounds__(128) synth_kernel(const float* __restrict__ params,
                                                    float* __restrict__ out) {
    int s = blockIdx.x, b = blockIdx.y;
    __shared__ float4 md[64];   // (ph_base_reduced, f0, dF, a0)
    __shared__ float  das[64];  // dA
    int tid = threadIdx.x;

    if (tid < 64) {
        int mode = tid;
        const float* F = params + (size_t)(b * 192 + mode) * 400;
        const float* A = F + 64 * 400;      // channel 1 = amps
        const float* P = F + 128 * 400;     // channel 2 = phase
        int i  = (s == 0) ? 0 : ((s <= 399) ? s - 1 : 399);
        int i1 = min(i + 1, 399);
        float f0 = F[i];
        float dw = F[i1] - f0;
        float a0 = A[i];
        float da = A[i1] - a0;
        // phase base = B[row][s] + phase[row][0], reduced mod 2pi in fp64 once
        double t = g_B[(size_t)(b * 64 + mode) * NSEG + s] + (double)P[0];
        double kk = rint(t * 0.15915494309189535);
        double rr = t - kk * 6.283185307179586;
        md[mode]  = make_float4((float)rr, f0, dw, a0);
        das[mode] = da;
    }
    __syncthreads();

    int cnt = (s == 0 || s == 400) ? 60 : 120;
    int m = tid;
    if (m >= cnt) return;
    int start = (s == 0) ? 0 : 60 + (s - 1) * 120;
    int j = start + m;

    float frac = ref_frac(j);               // exact ref-style frac (for amp interp)
    float F1s  = g_F1[s * 120 + m];         // Sum of frac within segment, inclusive
    float t1   = (float)(m + 1);

    const float INV2PI = 0.15915493667125702f;
    const float PI2_A  = 6.2831854820251465f;
    const float PI2_B  = -1.7484556e-07f;

    float acc = 0.0f;
#pragma unroll 16
    for (int k = 0; k < 64; k++) {
        float4 v = md[k];
        // S_j = ph_base + (m+1)*f0 + dF * SumFrac   (|ph| <= ~600)
        float ph = fmaf(v.z, F1s, fmaf(t1, v.y, v.x));
        // Cody-Waite reduce to [-pi, pi], then fast hardware sin (RRO+MUFU.SIN)
        float kr = rintf(ph * INV2PI);
        float r  = fmaf(-kr, PI2_A, ph);
        r        = fmaf(-kr, PI2_B, r);
        float a  = fmaf(das[k], frac, v.w);
        acc = fmaf(a, __sinf(r), acc);
    }
    out[(size_t)b * NS + j] = acc;
}

extern "C" void kernel_launch(void* const* d_in, const int* in_sizes, int n_in,
                              void* d_out, int out_size) {
    const float* params = (const float*)d_in[0];
    float* out = (float*)d_out;
    f1_kernel<<<NSEG, 128>>>();
    scan_kernel<<<NROWS, 512>>>(params);
    dim3 grid(NSEG, NB);
    synth_kernel<<<grid, 128>>>(params, out);
}

// round 3
// speedup vs baseline: 2.0068x; 1.1883x over previous
#include <cuda_runtime.h>

#define NS   48000
#define NIN  400
#define NSEG 401      // head(60) + 399 interior(120) + tail(60)
#define NB   16
#define NM   64
#define NROWS (NB*NM)

// Scratch (allocation-free): per-row fp64 segment prefixes + shared frac-cumsum table
__device__ double g_B[(size_t)NROWS * NSEG];   // ~3.3 MB
__device__ float  g_F1[NSEG * 120];            // 192 KB

// Exact replica of the reference's fp32 position/frac computation.
// Must NOT be FMA-contracted (ref does mul-then-sub with separate roundings).
__device__ __forceinline__ float ref_frac(int j) {
    const float SCALE = 400.0f / 48000.0f;   // fl32(1/120)
    float pos = __fsub_rn(__fmul_rn(__fadd_rn((float)j, 0.5f), SCALE), 0.5f);
    pos = fminf(fmaxf(pos, 0.0f), 399.0f);
    float fi = floorf(pos);
    return __fsub_rn(pos, fi);               // exact (Sterbenz)
}

// Kernel A: row-independent cumulative-frac table (one block per segment,
// 128-thread fp64 shuffle scan).
__global__ void __launch_bounds__(128) f1_kernel() {
    int s = blockIdx.x;
    int cnt   = (s == 0 || s == 400) ? 60 : 120;
    int start = (s == 0) ? 0 : 60 + (s - 1) * 120;
    int m = threadIdx.x;
    double v = (m < cnt) ? (double)ref_frac(start + m) : 0.0;

    int lane = m & 31, w = m >> 5;
    #pragma unroll
    for (int off = 1; off < 32; off <<= 1) {
        double n = __shfl_up_sync(0xFFFFFFFFu, v, off);
        if (lane >= off) v += n;
    }
    __shared__ double wsum[4];
    if (lane == 31) wsum[w] = v;
    __syncthreads();
    double base = 0.0;
    #pragma unroll
    for (int i = 0; i < 3; i++)
        if (i < w) base += wsum[i];
    if (m < cnt) g_F1[s * 120 + m] = (float)(v + base);
}

// Kernel B: per-row exclusive prefix over segment sums, fp64, shuffle-based.
// segsum(s) = cnt*f[i] + (f[i+1]-f[i]) * Sum(frac over segment)
__global__ void __launch_bounds__(512) scan_kernel(const float* __restrict__ params) {
    int r = blockIdx.x;                 // 0..1023 : b*64 + mode
    int b = r >> 6, mode = r & 63;
    const float* F = params + (size_t)(b * 192 + mode) * 400;  // channel 0 = freqs
    int t = threadIdx.x;                // 512 threads, values live in t=0..400

    double v = 0.0;
    if (t == 0) {
        v = 60.0 * (double)F[0];        // head: frac == 0 for all 60 samples
    } else if (t <= 399) {
        int i = t - 1;
        double f0 = F[i], f1 = F[i + 1];
        v = 120.0 * f0 + (f1 - f0) * (double)g_F1[t * 120 + 119];
    }

    int lane = t & 31, w = t >> 5;
    double sv = v;
    #pragma unroll
    for (int off = 1; off < 32; off <<= 1) {
        double n = __shfl_up_sync(0xFFFFFFFFu, sv, off);
        if (lane >= off) sv += n;
    }
    __shared__ double wsum[16];
    if (lane == 31) wsum[w] = sv;
    __syncthreads();
    if (w == 0) {
        double x = (lane < 16) ? wsum[lane] : 0.0;
        #pragma unroll
        for (int off = 1; off < 16; off <<= 1) {
            double n = __shfl_up_sync(0xFFFFFFFFu, x, off);
            if (lane >= off) x += n;
        }
        if (lane < 16) wsum[lane] = x;
    }
    __syncthreads();
    double incl = sv + ((w > 0) ? wsum[w - 1] : 0.0);
    if (t <= 400)
        g_B[(size_t)r * NSEG + t] = incl - v;   // exclusive prefix
}

// Kernel C: main synthesis. Block = (segment s, batch b); thread = sample m.
// Inner loop is 4 FFMA + 1 MUFU.SIN + 2 broadcast LDS per mode — co-bound on
// the fma and MUFU pipes (~8 cyc/iter/SMSP). MUFU.SIN does its own range
// reduction (|ph| <= ~600 -> abs err ~5e-5, well inside budget).
__global__ void __launch_bounds__(128) synth_kernel(const float* __restrict__ params,
                                                    float* __restrict__ out) {
    int s = blockIdx.x, b = blockIdx.y;
    __shared__ float4 md[64];   // (ph_base_reduced, f0, dF, a0)
    __shared__ float  das[64];  // dA
    int tid = threadIdx.x;

    if (tid < 64) {
        int mode = tid;
        const float* F = params + (size_t)(b * 192 + mode) * 400;
        const float* A = F + 64 * 400;      // channel 1 = amps
        const float* P = F + 128 * 400;     // channel 2 = phase
        int i  = (s == 0) ? 0 : ((s <= 399) ? s - 1 : 399);
        int i1 = min(i + 1, 399);
        float f0 = F[i];
        float dw = F[i1] - f0;
        float a0 = A[i];
        float da = A[i1] - a0;
        // phase base = B[row][s] + phase[row][0], reduced mod 2pi in fp64 once
        double t = g_B[(size_t)(b * 64 + mode) * NSEG + s] + (double)P[0];
        double kk = rint(t * 0.15915494309189535);
        double rr = t - kk * 6.283185307179586;
        md[mode]  = make_float4((float)rr, f0, dw, a0);
        das[mode] = da;
    }
    __syncthreads();

    int cnt = (s == 0 || s == 400) ? 60 : 120;
    int m = tid;
    if (m >= cnt) return;
    int start = (s == 0) ? 0 : 60 + (s - 1) * 120;
    int j = start + m;

    float frac = ref_frac(j);               // exact ref-style frac (for amp interp)
    float F1s  = g_F1[s * 120 + m];         // Sum of frac within segment, inclusive
    float t1   = (float)(m + 1);

    float acc = 0.0f;
#pragma unroll 16
    for (int k = 0; k < 64; k++) {
        float4 v = md[k];
        // S_j = ph_base + (m+1)*f0 + dF * SumFrac   (|ph| <= ~600)
        float ph = fmaf(v.z, F1s, fmaf(t1, v.y, v.x));
        float a  = fmaf(das[k], frac, v.w);
        acc = fmaf(a, __sinf(ph), acc);     // MUFU.SIN handles range reduction
    }
    out[(size_t)b * NS + j] = acc;
}

extern "C" void kernel_launch(void* const* d_in, const int* in_sizes, int n_in,
                              void* d_out, int out_size) {
    const float* params = (const float*)d_in[0];
    float* out = (float*)d_out;
    f1_kernel<<<NSEG, 128>>>();
    scan_kernel<<<NROWS, 512>>>(params);
    dim3 grid(NSEG, NB);
    synth_kernel<<<grid, 128>>>(params, out);
}

// round 4
// speedup vs baseline: 2.0088x; 1.0010x over previous
#include <cuda_runtime.h>

#define NS   48000
#define NIN  400
#define NSEG 401      // head(60) + 399 interior(120) + tail(60)
#define NB   16
#define NM   64
#define NROWS (NB*NM)

typedef unsigned long long u64;

// Scratch (allocation-free)
__device__ double g_B[(size_t)NROWS * NSEG];   // per-row fp64 segment prefixes
__device__ float  g_F1[NSEG * 120];            // shared frac-cumsum table

// ---- f32x2 helpers (Blackwell packed fp32) ----
__device__ __forceinline__ u64 fma2(u64 a, u64 b, u64 c) {
    u64 d;
    asm("fma.rn.f32x2 %0, %1, %2, %3;" : "=l"(d) : "l"(a), "l"(b), "l"(c));
    return d;
}
__device__ __forceinline__ u64 pk(float lo, float hi) {
    u64 r; asm("mov.b64 %0, {%1,%2};" : "=l"(r) : "f"(lo), "f"(hi)); return r;
}
__device__ __forceinline__ void upk(u64 v, float& lo, float& hi) {
    asm("mov.b64 {%0,%1}, %2;" : "=f"(lo), "=f"(hi) : "l"(v));
}

// Exact replica of the reference's fp32 position/frac computation.
__device__ __forceinline__ float ref_frac(int j) {
    const float SCALE = 400.0f / 48000.0f;   // fl32(1/120)
    float pos = __fsub_rn(__fmul_rn(__fadd_rn((float)j, 0.5f), SCALE), 0.5f);
    pos = fminf(fmaxf(pos, 0.0f), 399.0f);
    float fi = floorf(pos);
    return __fsub_rn(pos, fi);               // exact (Sterbenz)
}

// Kernel A: row-independent cumulative-frac table (one block per segment).
__global__ void __launch_bounds__(128) f1_kernel() {
    int s = blockIdx.x;
    int cnt   = (s == 0 || s == 400) ? 60 : 120;
    int start = (s == 0) ? 0 : 60 + (s - 1) * 120;
    int m = threadIdx.x;
    double v = (m < cnt) ? (double)ref_frac(start + m) : 0.0;

    int lane = m & 31, w = m >> 5;
    #pragma unroll
    for (int off = 1; off < 32; off <<= 1) {
        double n = __shfl_up_sync(0xFFFFFFFFu, v, off);
        if (lane >= off) v += n;
    }
    __shared__ double wsum[4];
    if (lane == 31) wsum[w] = v;
    __syncthreads();
    double base = 0.0;
    #pragma unroll
    for (int i = 0; i < 3; i++)
        if (i < w) base += wsum[i];
    if (m < cnt) g_F1[s * 120 + m] = (float)(v + base);
    else if (m < 120) g_F1[s * 120 + m] = 0.0f;  // keep table finite everywhere
}

// Kernel B: per-row exclusive prefix over segment sums, fp64, shuffle-based.
__global__ void __launch_bounds__(512) scan_kernel(const float* __restrict__ params) {
    int r = blockIdx.x;                 // 0..1023 : b*64 + mode
    int b = r >> 6, mode = r & 63;
    const float* F = params + (size_t)(b * 192 + mode) * 400;  // channel 0 = freqs
    int t = threadIdx.x;

    double v = 0.0;
    if (t == 0) {
        v = 60.0 * (double)F[0];        // head: frac == 0 for all 60 samples
    } else if (t <= 399) {
        int i = t - 1;
        double f0 = F[i], f1 = F[i + 1];
        v = 120.0 * f0 + (f1 - f0) * (double)g_F1[t * 120 + 119];
    }

    int lane = t & 31, w = t >> 5;
    double sv = v;
    #pragma unroll
    for (int off = 1; off < 32; off <<= 1) {
        double n = __shfl_up_sync(0xFFFFFFFFu, sv, off);
        if (lane >= off) sv += n;
    }
    __shared__ double wsum[16];
    if (lane == 31) wsum[w] = sv;
    __syncthreads();
    if (w == 0) {
        double x = (lane < 16) ? wsum[lane] : 0.0;
        #pragma unroll
        for (int off = 1; off < 16; off <<= 1) {
            double n = __shfl_up_sync(0xFFFFFFFFu, x, off);
            if (lane >= off) x += n;
        }
        if (lane < 16) wsum[lane] = x;
    }
    __syncthreads();
    double incl = sv + ((w > 0) ? wsum[w - 1] : 0.0);
    if (t <= 400)
        g_B[(size_t)r * NSEG + t] = incl - v;   // exclusive prefix
}

// Kernel C: synthesis. Block=(segment s, batch b), 64 threads.
// Thread m computes samples (m, m+60) of the segment with packed f32x2 math.
// Inner loop per 2 mode-samples: 3 LDS + 4 FFMA2 + 2 MUFU -> MUFU-bound.
__global__ void __launch_bounds__(64) synth_kernel(const float* __restrict__ params,
                                                   float* __restrict__ out) {
    int s = blockIdx.x, b = blockIdx.y;
    __shared__ float4 md0[64];   // {ph,ph, f0,f0}
    __shared__ float4 md1[64];   // {dF,dF, a0,a0}
    __shared__ float2 md2[64];   // {da,da}
    int tid = threadIdx.x;

    {
        int mode = tid;          // 64 threads == 64 modes
        const float* F = params + (size_t)(b * 192 + mode) * 400;
        const float* A = F + 64 * 400;      // channel 1 = amps
        const float* P = F + 128 * 400;     // channel 2 = phase
        int i  = (s == 0) ? 0 : ((s <= 399) ? s - 1 : 399);
        int i1 = min(i + 1, 399);
        float f0 = F[i];
        float dw = F[i1] - f0;
        float a0 = A[i];
        float da = A[i1] - a0;
        // phase base = B[row][s] + phase[row][0], reduced mod 2pi in fp64 once
        double t = g_B[(size_t)(b * 64 + mode) * NSEG + s] + (double)P[0];
        double kk = rint(t * 0.15915494309189535);
        double rr = t - kk * 6.283185307179586;
        float ph = (float)rr;
        md0[mode] = make_float4(ph, ph, f0, f0);
        md1[mode] = make_float4(dw, dw, a0, a0);
        md2[mode] = make_float2(da, da);
    }
    __syncthreads();

    int m = tid;
    if (m >= 60) return;                    // 60 threads x 2 samples = 120
    bool interior = (s != 0 && s != 400);
    int start = (s == 0) ? 0 : 60 + (s - 1) * 120;
    int j0 = start + m;
    int j1 = start + m + 60;                // valid only for interior segments

    u64 t1p   = pk((float)(m + 1), (float)(m + 61));
    u64 f1p   = pk(g_F1[s * 120 + m], g_F1[s * 120 + m + 60]);
    u64 fracp = pk(ref_frac(j0), interior ? ref_frac(j1) : 0.0f);

    const ulonglong2* M0 = (const ulonglong2*)md0;
    const ulonglong2* M1 = (const ulonglong2*)md1;
    const u64*        M2 = (const u64*)md2;

    u64 acc2 = pk(0.0f, 0.0f);
#pragma unroll 8
    for (int k = 0; k < 64; k++) {
        ulonglong2 q0 = M0[k];              // q0.x=(ph,ph) q0.y=(f0,f0)
        ulonglong2 q1 = M1[k];              // q1.x=(dF,dF) q1.y=(a0,a0)
        u64 dd = M2[k];                     // (da,da)
        u64 ph2 = fma2(t1p, q0.y, q0.x);    // ph + t1*f0
        ph2     = fma2(f1p, q1.x, ph2);     // + F1s*dF
        u64 a2  = fma2(fracp, dd, q1.y);    // a0 + frac*da
        float plo, phi; upk(ph2, plo, phi);
        u64 s2 = pk(__sinf(plo), __sinf(phi));
        acc2 = fma2(a2, s2, acc2);
    }

    float alo, ahi; upk(acc2, alo, ahi);
    out[(size_t)b * NS + j0] = alo;
    if (interior) out[(size_t)b * NS + j1] = ahi;
}

extern "C" void kernel_launch(void* const* d_in, const int* in_sizes, int n_in,
                              void* d_out, int out_size) {
    const float* params = (const float*)d_in[0];
    float* out = (float*)d_out;
    f1_kernel<<<NSEG, 128>>>();
    scan_kernel<<<NROWS, 512>>>(params);
    dim3 grid(NSEG, NB);
    synth_kernel<<<grid, 64>>>(params, out);
}